// round 8
// baseline (speedup 1.0000x reference)
#include <cuda_runtime.h>

// Operator3D: bs=4, v=8192, n=20, SUPPORT=4, KERNEL=32  (S*K = 128)
// inputs: [0] neighbor_index int32 (bs,v,n)
//         [1] vertices       f32   (bs,v,3)
//         [2] weights        f32   (1,1,4,32)
//         [3] displacement   f32   (3,128)
// output: feature f32 (bs,v,32)
//
// FFMA-pipe-bound body (issue ceiling 1/(2*ffma_density)) -> use fma.rn.f32x2
// to halve pipe occupancy, with TWO neighbors per unrolled step so there are
// 4 independent packed chains (R5 failed with only 2). Packed (d,d) operand
// pairs are built by the gather lanes and stored duplicated in smem, so the
// hot loop has zero pack/unpack ALU work: 2 LDS + 6 FFMA2 + 4 FMNMX per nbr.
// Shell identical to R7: warp-per-2-rows, batched gather, idx prefetch,
// grid = 740 = 5 blocks/SM * 148.

#define BS_   4
#define V_    8192
#define N_    20
#define K_    32
#define SK_   128
#define ROWS_ (BS_ * V_)

#define GR_      2
#define GITEMS_  (GR_ * N_)            // 40
#define GROUPS_  (ROWS_ / GR_)         // 16384

#define WPB      8
#define THREADS_ (WPB * 32)
#define BLOCKS_  740                   // 5 blocks/SM * 148 -> one full wave
#define NWARPS_  (BLOCKS_ * WPB)       // 5920

typedef unsigned long long u64;

__device__ __forceinline__ u64 packf2(float lo, float hi) {
    u64 r;
    asm("mov.b64 %0, {%1, %2};" : "=l"(r) : "f"(lo), "f"(hi));
    return r;
}
__device__ __forceinline__ void unpackf2(float& lo, float& hi, u64 v) {
    asm("mov.b64 {%0, %1}, %2;" : "=f"(lo), "=f"(hi) : "l"(v));
}
#define FMA_F32X2(out, a, b, c) \
    asm("fma.rn.f32x2 %0, %1, %2, %3;" : "=l"(out) : "l"(a), "l"(b), "l"(c))
#define MUL_F32X2_(out, a, b) \
    asm("mul.rn.f32x2 %0, %1, %2;" : "=l"(out) : "l"(a), "l"(b))

// 32B per neighbor: (dx,dx) (dy,dy) (dz,dz) pad — 16B aligned for v2.b64
struct __align__(16) Nbr { u64 x2, y2, z2, pad; };

__global__ __launch_bounds__(THREADS_, 5)
void op3d_kernel(const int*   __restrict__ nb,
                 const float* __restrict__ verts,
                 const float* __restrict__ weights,
                 const float* __restrict__ disp,
                 float*       __restrict__ out)
{
    __shared__ Nbr sd[WPB][GITEMS_];

    const int warp  = threadIdx.x >> 5;
    const int lane  = threadIdx.x & 31;
    const int gwarp = blockIdx.x * WPB + warp;

    // Support-paired displacement columns: 6 u64 = 12 regs.
    const u64 D0_01 = packf2(disp[0*SK_ +  0 + lane], disp[0*SK_ + 32 + lane]);
    const u64 D0_23 = packf2(disp[0*SK_ + 64 + lane], disp[0*SK_ + 96 + lane]);
    const u64 D1_01 = packf2(disp[1*SK_ +  0 + lane], disp[1*SK_ + 32 + lane]);
    const u64 D1_23 = packf2(disp[1*SK_ + 64 + lane], disp[1*SK_ + 96 + lane]);
    const u64 D2_01 = packf2(disp[2*SK_ +  0 + lane], disp[2*SK_ + 32 + lane]);
    const u64 D2_23 = packf2(disp[2*SK_ + 64 + lane], disp[2*SK_ + 96 + lane]);
    const float w0 = weights[ 0 + lane];
    const float w1 = weights[32 + lane];
    const float w2 = weights[64 + lane];
    const float w3 = weights[96 + lane];

    const unsigned sbase = (unsigned)__cvta_generic_to_shared(&sd[warp][0]);
    const bool hasExtra  = (lane < GITEMS_ - 32);     // lanes 0..7

    int g = gwarp;

    int i0 = 0, i1 = 0;
    if (g < GROUPS_) {
        const int gb = g * GITEMS_;
        i0 = nb[gb + lane];
        if (hasExtra) i1 = nb[gb + 32 + lane];
    }

    while (g < GROUPS_) {
        const int r0    = g * GR_;
        const int vbase = (r0 >> 13) * (V_ * 3);

        // 1) prefetch next group's indices (independent LDGs in flight)
        const int gn = g + NWARPS_;
        int n0 = 0, n1 = 0;
        if (gn < GROUPS_) {
            const int gbn = gn * GITEMS_;
            n0 = nb[gbn + lane];
            if (hasExtra) n1 = nb[gbn + 32 + lane];
        }

        // 2) batched gather; store duplicated pairs (pack off the hot path)
        {
            const int   row0 = (lane >= N_);
            const float* p0  = verts + vbase + i0 * 3;
            const float* q0  = verts + (r0 + row0) * 3;
            float dx = p0[0]-q0[0], dy = p0[1]-q0[1], dz = p0[2]-q0[2];
            unsigned a = sbase + (unsigned)lane * sizeof(Nbr);
            asm volatile("st.shared.v2.b64 [%0], {%1, %2};"
                         :: "r"(a), "l"(packf2(dx,dx)), "l"(packf2(dy,dy)));
            asm volatile("st.shared.b64 [%0], %1;"
                         :: "r"(a + 16), "l"(packf2(dz,dz)));
            if (hasExtra) {
                const float* p1 = verts + vbase + i1 * 3;
                const float* q1 = verts + (r0 + 1) * 3;
                float ex = p1[0]-q1[0], ey = p1[1]-q1[1], ez = p1[2]-q1[2];
                unsigned b = sbase + (unsigned)(lane + 32) * sizeof(Nbr);
                asm volatile("st.shared.v2.b64 [%0], {%1, %2};"
                             :: "r"(b), "l"(packf2(ex,ex)), "l"(packf2(ey,ey)));
                asm volatile("st.shared.b64 [%0], %1;"
                             :: "r"(b + 16), "l"(packf2(ez,ez)));
            }
        }
        __syncwarp();

        // 3) compute: 2 rows; per step TWO neighbors -> 4 independent chains
        #pragma unroll 1
        for (int row = 0; row < GR_; row++) {
            float m0 = 0.0f, m1 = 0.0f, m2 = 0.0f, m3 = 0.0f;
            const unsigned rb = sbase + (unsigned)(row * N_) * sizeof(Nbr);
            #pragma unroll
            for (int j = 0; j < N_; j += 2) {
                const unsigned a = rb + (unsigned)j * sizeof(Nbr);
                u64 ax2, ay2, az2, bx2, by2, bz2;
                asm("ld.shared.v2.b64 {%0, %1}, [%2];"
                    : "=l"(ax2), "=l"(ay2) : "r"(a));
                asm("ld.shared.b64 %0, [%1];"
                    : "=l"(az2) : "r"(a + 16));
                asm("ld.shared.v2.b64 {%0, %1}, [%2];"
                    : "=l"(bx2), "=l"(by2) : "r"(a + 32));
                asm("ld.shared.b64 %0, [%1];"
                    : "=l"(bz2) : "r"(a + 48));

                u64 ta01, ta23, tb01, tb23;
                MUL_F32X2_(ta01, az2, D2_01);
                MUL_F32X2_(ta23, az2, D2_23);
                MUL_F32X2_(tb01, bz2, D2_01);
                MUL_F32X2_(tb23, bz2, D2_23);
                FMA_F32X2(ta01, ay2, D1_01, ta01);
                FMA_F32X2(ta23, ay2, D1_23, ta23);
                FMA_F32X2(tb01, by2, D1_01, tb01);
                FMA_F32X2(tb23, by2, D1_23, tb23);
                FMA_F32X2(ta01, ax2, D0_01, ta01);
                FMA_F32X2(ta23, ax2, D0_23, ta23);
                FMA_F32X2(tb01, bx2, D0_01, tb01);
                FMA_F32X2(tb23, bx2, D0_23, tb23);

                float t0, t1, t2, t3, u0, u1, u2, u3;
                unpackf2(t0, t1, ta01);
                unpackf2(t2, t3, ta23);
                unpackf2(u0, u1, tb01);
                unpackf2(u2, u3, tb23);
                m0 = fmaxf(fmaxf(m0, t0), u0);
                m1 = fmaxf(fmaxf(m1, t1), u1);
                m2 = fmaxf(fmaxf(m2, t2), u2);
                m3 = fmaxf(fmaxf(m3, t3), u3);
            }
            out[(r0 + row) * K_ + lane] =
                fmaf(m0, w0, fmaf(m1, w1, fmaf(m2, w2, m3 * w3)));
        }

        g  = gn;
        i0 = n0;
        i1 = n1;
        __syncwarp();
    }
}

extern "C" void kernel_launch(void* const* d_in, const int* in_sizes, int n_in,
                              void* d_out, int out_size)
{
    const int*   nb      = (const int*)  d_in[0];
    const float* verts   = (const float*)d_in[1];
    const float* weights = (const float*)d_in[2];
    const float* disp    = (const float*)d_in[3];
    float*       out     = (float*)      d_out;

    op3d_kernel<<<BLOCKS_, THREADS_>>>(nb, verts, weights, disp, out);
}

// round 9
// speedup vs baseline: 1.3535x; 1.3535x over previous
#include <cuda_runtime.h>

// Operator3D: bs=4, v=8192, n=20, SUPPORT=4, KERNEL=32  (S*K = 128)
// inputs: [0] neighbor_index int32 (bs,v,n)
//         [1] vertices       f32   (bs,v,3)
//         [2] weights        f32   (1,1,4,32)
//         [3] displacement   f32   (3,128)
// output: feature f32 (bs,v,32)
//
// Warp-per-2-rows with batched gather (proven R7 shell). NEW: the two rows'
// compute is FUSED into one inner loop over j: per iteration 2 independent
// LDS.128 + 24 scalar FFMA across 8 independent max-accumulator chains.
// Doubles ILP between LDS waits (R4/R7 had only 4 chains per LDS), attacking
// the ~7K-cycle dependency-stall gap between measured 34.8K cyc and the
// ~27.4K cyc FFMA-pipe floor. f32x2 abandoned (3 failures: frees issue slots
// but not FMA-pipe cycles).

#define BS_   4
#define V_    8192
#define N_    20
#define K_    32
#define SK_   128
#define ROWS_ (BS_ * V_)

#define GR_      2
#define GITEMS_  (GR_ * N_)            // 40
#define GROUPS_  (ROWS_ / GR_)         // 16384

#define WPB      8
#define THREADS_ (WPB * 32)
#define BLOCKS_  740                   // 5 blocks/SM * 148
#define NWARPS_  (BLOCKS_ * WPB)       // 5920

__global__ __launch_bounds__(THREADS_, 4)   // allow ~56-64 regs: ILP > occupancy here
void op3d_kernel(const int*   __restrict__ nb,
                 const float* __restrict__ verts,
                 const float* __restrict__ weights,
                 const float* __restrict__ disp,
                 float*       __restrict__ out)
{
    __shared__ float4 sd[WPB][GITEMS_];

    const int warp  = threadIdx.x >> 5;
    const int lane  = threadIdx.x & 31;
    const int gwarp = blockIdx.x * WPB + warp;

    // Per-lane constants: displacement columns for k = s*32 + lane, s=0..3.
    const float d00 = disp[0 * SK_ +  0 + lane];
    const float d01 = disp[0 * SK_ + 32 + lane];
    const float d02 = disp[0 * SK_ + 64 + lane];
    const float d03 = disp[0 * SK_ + 96 + lane];
    const float d10 = disp[1 * SK_ +  0 + lane];
    const float d11 = disp[1 * SK_ + 32 + lane];
    const float d12 = disp[1 * SK_ + 64 + lane];
    const float d13 = disp[1 * SK_ + 96 + lane];
    const float d20 = disp[2 * SK_ +  0 + lane];
    const float d21 = disp[2 * SK_ + 32 + lane];
    const float d22 = disp[2 * SK_ + 64 + lane];
    const float d23 = disp[2 * SK_ + 96 + lane];
    const float w0  = weights[ 0 + lane];
    const float w1  = weights[32 + lane];
    const float w2  = weights[64 + lane];
    const float w3  = weights[96 + lane];

    const bool hasExtra = (lane < GITEMS_ - 32);   // lanes 0..7

    int g = gwarp;

    // prologue: first group's indices (2 coalesced LDGs)
    int i0 = 0, i1 = 0;
    if (g < GROUPS_) {
        const int gb = g * GITEMS_;
        i0 = nb[gb + lane];
        if (hasExtra) i1 = nb[gb + 32 + lane];
    }

    while (g < GROUPS_) {
        const int r0    = g * GR_;
        const int vbase = (r0 >> 13) * (V_ * 3);   // groups never span batches

        // 1) prefetch next group's indices (independent LDGs go in flight)
        const int gn = g + NWARPS_;
        int n0 = 0, n1 = 0;
        if (gn < GROUPS_) {
            const int gbn = gn * GITEMS_;
            n0 = nb[gbn + lane];
            if (hasExtra) n1 = nb[gbn + 32 + lane];
        }

        // 2) batched gather for current group (idx already resident)
        {
            const int   row0 = (lane >= N_);           // item = lane
            const float* p0  = verts + vbase + i0 * 3;
            const float* q0  = verts + (r0 + row0) * 3;
            sd[warp][lane] = make_float4(p0[0]-q0[0], p0[1]-q0[1],
                                         p0[2]-q0[2], 0.0f);
            if (hasExtra) {                            // item = lane+32 -> row 1
                const float* p1 = verts + vbase + i1 * 3;
                const float* q1 = verts + (r0 + 1) * 3;
                sd[warp][lane + 32] = make_float4(p1[0]-q1[0], p1[1]-q1[1],
                                                  p1[2]-q1[2], 0.0f);
            }
        }
        __syncwarp();

        // 3) FUSED compute for both rows: 8 independent max chains,
        //    2 independent LDS.128 per iteration. max seeded 0 == relu.
        float a0=0.f, a1=0.f, a2=0.f, a3=0.f;     // row 0
        float b0=0.f, b1=0.f, b2=0.f, b3=0.f;     // row 1
        {
            const float4* s0 = &sd[warp][0];
            const float4* s1 = &sd[warp][N_];
            #pragma unroll
            for (int j = 0; j < N_; j++) {
                const float4 da = s0[j];
                const float4 db = s1[j];

                float ta0 = fmaf(da.x, d00, fmaf(da.y, d10, da.z * d20));
                float tb0 = fmaf(db.x, d00, fmaf(db.y, d10, db.z * d20));
                float ta1 = fmaf(da.x, d01, fmaf(da.y, d11, da.z * d21));
                float tb1 = fmaf(db.x, d01, fmaf(db.y, d11, db.z * d21));
                float ta2 = fmaf(da.x, d02, fmaf(da.y, d12, da.z * d22));
                float tb2 = fmaf(db.x, d02, fmaf(db.y, d12, db.z * d22));
                float ta3 = fmaf(da.x, d03, fmaf(da.y, d13, da.z * d23));
                float tb3 = fmaf(db.x, d03, fmaf(db.y, d13, db.z * d23));

                a0 = fmaxf(a0, ta0);  b0 = fmaxf(b0, tb0);
                a1 = fmaxf(a1, ta1);  b1 = fmaxf(b1, tb1);
                a2 = fmaxf(a2, ta2);  b2 = fmaxf(b2, tb2);
                a3 = fmaxf(a3, ta3);  b3 = fmaxf(b3, tb3);
            }
        }

        out[ r0      * K_ + lane] = fmaf(a0, w0, fmaf(a1, w1, fmaf(a2, w2, a3 * w3)));
        out[(r0 + 1) * K_ + lane] = fmaf(b0, w0, fmaf(b1, w1, fmaf(b2, w2, b3 * w3)));

        g  = gn;
        i0 = n0;
        i1 = n1;
        __syncwarp();   // protect smem before next group's stores
    }
}

extern "C" void kernel_launch(void* const* d_in, const int* in_sizes, int n_in,
                              void* d_out, int out_size)
{
    const int*   nb      = (const int*)  d_in[0];
    const float* verts   = (const float*)d_in[1];
    const float* weights = (const float*)d_in[2];
    const float* disp    = (const float*)d_in[3];
    float*       out     = (float*)      d_out;

    op3d_kernel<<<BLOCKS_, THREADS_>>>(nb, verts, weights, disp, out);
}

// round 10
// speedup vs baseline: 1.3659x; 1.0091x over previous
#include <cuda_runtime.h>

// Operator3D: bs=4, v=8192, n=20, SUPPORT=4, KERNEL=32  (S*K = 128)
// inputs: [0] neighbor_index int32 (bs,v,n)
//         [1] vertices       f32   (bs,v,3)
//         [2] weights        f32   (1,1,4,32)
//         [3] displacement   f32   (3,128)
// output: feature f32 (bs,v,32)
//
// R9 fused body (best measured: issue 70.7%) with FIXED launch geometry:
// grid = 592 = exactly 4 blocks/SM * 148 SMs at launch_bounds(256,4), so all
// blocks are resident from cycle 0 and there is no second-wave tail (R4/R9
// ran 1.25-1.4 ragged waves). Warp-per-2-rows, batched gather, idx prefetch,
// fused 2-row compute: 2 LDS.128 + 24 FFMA + 8 FMNMX per j over 8 chains.

#define BS_   4
#define V_    8192
#define N_    20
#define K_    32
#define SK_   128
#define ROWS_ (BS_ * V_)

#define GR_      2
#define GITEMS_  (GR_ * N_)            // 40
#define GROUPS_  (ROWS_ / GR_)         // 16384

#define WPB      8
#define THREADS_ (WPB * 32)
#define BLOCKS_  592                   // 4 blocks/SM * 148 -> ONE exact wave
#define NWARPS_  (BLOCKS_ * WPB)       // 4736 warps, 3-4 groups each

__global__ __launch_bounds__(THREADS_, 4)
void op3d_kernel(const int*   __restrict__ nb,
                 const float* __restrict__ verts,
                 const float* __restrict__ weights,
                 const float* __restrict__ disp,
                 float*       __restrict__ out)
{
    __shared__ float4 sd[WPB][GITEMS_];

    const int warp  = threadIdx.x >> 5;
    const int lane  = threadIdx.x & 31;
    const int gwarp = blockIdx.x * WPB + warp;

    // Per-lane constants: displacement columns for k = s*32 + lane, s=0..3.
    const float d00 = disp[0 * SK_ +  0 + lane];
    const float d01 = disp[0 * SK_ + 32 + lane];
    const float d02 = disp[0 * SK_ + 64 + lane];
    const float d03 = disp[0 * SK_ + 96 + lane];
    const float d10 = disp[1 * SK_ +  0 + lane];
    const float d11 = disp[1 * SK_ + 32 + lane];
    const float d12 = disp[1 * SK_ + 64 + lane];
    const float d13 = disp[1 * SK_ + 96 + lane];
    const float d20 = disp[2 * SK_ +  0 + lane];
    const float d21 = disp[2 * SK_ + 32 + lane];
    const float d22 = disp[2 * SK_ + 64 + lane];
    const float d23 = disp[2 * SK_ + 96 + lane];
    const float w0  = weights[ 0 + lane];
    const float w1  = weights[32 + lane];
    const float w2  = weights[64 + lane];
    const float w3  = weights[96 + lane];

    const bool hasExtra = (lane < GITEMS_ - 32);   // lanes 0..7

    int g = gwarp;

    // prologue: first group's indices (2 coalesced LDGs)
    int i0 = 0, i1 = 0;
    if (g < GROUPS_) {
        const int gb = g * GITEMS_;
        i0 = nb[gb + lane];
        if (hasExtra) i1 = nb[gb + 32 + lane];
    }

    while (g < GROUPS_) {
        const int r0    = g * GR_;
        const int vbase = (r0 >> 13) * (V_ * 3);   // groups never span batches

        // 1) prefetch next group's indices (independent LDGs go in flight)
        const int gn = g + NWARPS_;
        int n0 = 0, n1 = 0;
        if (gn < GROUPS_) {
            const int gbn = gn * GITEMS_;
            n0 = nb[gbn + lane];
            if (hasExtra) n1 = nb[gbn + 32 + lane];
        }

        // 2) batched gather for current group (idx already resident)
        {
            const int   row0 = (lane >= N_);           // item = lane
            const float* p0  = verts + vbase + i0 * 3;
            const float* q0  = verts + (r0 + row0) * 3;
            sd[warp][lane] = make_float4(p0[0]-q0[0], p0[1]-q0[1],
                                         p0[2]-q0[2], 0.0f);
            if (hasExtra) {                            // item = lane+32 -> row 1
                const float* p1 = verts + vbase + i1 * 3;
                const float* q1 = verts + (r0 + 1) * 3;
                sd[warp][lane + 32] = make_float4(p1[0]-q1[0], p1[1]-q1[1],
                                                  p1[2]-q1[2], 0.0f);
            }
        }
        __syncwarp();

        // 3) FUSED compute for both rows: 8 independent max chains,
        //    2 independent LDS.128 per iteration. max seeded 0 == relu.
        float a0=0.f, a1=0.f, a2=0.f, a3=0.f;     // row 0
        float b0=0.f, b1=0.f, b2=0.f, b3=0.f;     // row 1
        {
            const float4* s0 = &sd[warp][0];
            const float4* s1 = &sd[warp][N_];
            #pragma unroll
            for (int j = 0; j < N_; j++) {
                const float4 da = s0[j];
                const float4 db = s1[j];

                float ta0 = fmaf(da.x, d00, fmaf(da.y, d10, da.z * d20));
                float tb0 = fmaf(db.x, d00, fmaf(db.y, d10, db.z * d20));
                float ta1 = fmaf(da.x, d01, fmaf(da.y, d11, da.z * d21));
                float tb1 = fmaf(db.x, d01, fmaf(db.y, d11, db.z * d21));
                float ta2 = fmaf(da.x, d02, fmaf(da.y, d12, da.z * d22));
                float tb2 = fmaf(db.x, d02, fmaf(db.y, d12, db.z * d22));
                float ta3 = fmaf(da.x, d03, fmaf(da.y, d13, da.z * d23));
                float tb3 = fmaf(db.x, d03, fmaf(db.y, d13, db.z * d23));

                a0 = fmaxf(a0, ta0);  b0 = fmaxf(b0, tb0);
                a1 = fmaxf(a1, ta1);  b1 = fmaxf(b1, tb1);
                a2 = fmaxf(a2, ta2);  b2 = fmaxf(b2, tb2);
                a3 = fmaxf(a3, ta3);  b3 = fmaxf(b3, tb3);
            }
        }

        out[ r0      * K_ + lane] = fmaf(a0, w0, fmaf(a1, w1, fmaf(a2, w2, a3 * w3)));
        out[(r0 + 1) * K_ + lane] = fmaf(b0, w0, fmaf(b1, w1, fmaf(b2, w2, b3 * w3)));

        g  = gn;
        i0 = n0;
        i1 = n1;
        __syncwarp();   // protect smem before next group's stores
    }
}

extern "C" void kernel_launch(void* const* d_in, const int* in_sizes, int n_in,
                              void* d_out, int out_size)
{
    const int*   nb      = (const int*)  d_in[0];
    const float* verts   = (const float*)d_in[1];
    const float* weights = (const float*)d_in[2];
    const float* disp    = (const float*)d_in[3];
    float*       out     = (float*)      d_out;

    op3d_kernel<<<BLOCKS_, THREADS_>>>(nb, verts, weights, disp, out);
}

// round 11
// speedup vs baseline: 1.3679x; 1.0015x over previous
#include <cuda_runtime.h>

// Operator3D: bs=4, v=8192, n=20, SUPPORT=4, KERNEL=32  (S*K = 128)
// inputs: [0] neighbor_index int32 (bs,v,n)
//         [1] vertices       f32   (bs,v,3)
//         [2] weights        f32   (1,1,4,32)
//         [3] displacement   f32   (3,128)
// output: feature f32 (bs,v,32)
//
// R9 fused body (best: issue 70.7%) with a PERFECTLY BALANCED schedule:
// 512 blocks * 8 warps = 4096 warps, 16384 groups -> EXACTLY 4 groups per
// warp (R9 had 2.77 avg -> 8% tail; R10 had 3.46 -> 16% tail, which is why
// the "exact wave" grid was slower). Constant trip count also lets the
// compiler pipeline next-group gather into current-group compute.

#define BS_   4
#define V_    8192
#define N_    20
#define K_    32
#define SK_   128
#define ROWS_ (BS_ * V_)

#define GR_      2
#define GITEMS_  (GR_ * N_)            // 40
#define GROUPS_  (ROWS_ / GR_)         // 16384

#define WPB      8
#define THREADS_ (WPB * 32)
#define BLOCKS_  512                   // 4096 warps -> exactly 4 groups each
#define NWARPS_  (BLOCKS_ * WPB)
#define GPW_     (GROUPS_ / NWARPS_)   // 4, exact

__global__ __launch_bounds__(THREADS_, 4)
void op3d_kernel(const int*   __restrict__ nb,
                 const float* __restrict__ verts,
                 const float* __restrict__ weights,
                 const float* __restrict__ disp,
                 float*       __restrict__ out)
{
    __shared__ float4 sd[WPB][GITEMS_];

    const int warp  = threadIdx.x >> 5;
    const int lane  = threadIdx.x & 31;
    const int gwarp = blockIdx.x * WPB + warp;

    // Per-lane constants: displacement columns for k = s*32 + lane, s=0..3.
    const float d00 = disp[0 * SK_ +  0 + lane];
    const float d01 = disp[0 * SK_ + 32 + lane];
    const float d02 = disp[0 * SK_ + 64 + lane];
    const float d03 = disp[0 * SK_ + 96 + lane];
    const float d10 = disp[1 * SK_ +  0 + lane];
    const float d11 = disp[1 * SK_ + 32 + lane];
    const float d12 = disp[1 * SK_ + 64 + lane];
    const float d13 = disp[1 * SK_ + 96 + lane];
    const float d20 = disp[2 * SK_ +  0 + lane];
    const float d21 = disp[2 * SK_ + 32 + lane];
    const float d22 = disp[2 * SK_ + 64 + lane];
    const float d23 = disp[2 * SK_ + 96 + lane];
    const float w0  = weights[ 0 + lane];
    const float w1  = weights[32 + lane];
    const float w2  = weights[64 + lane];
    const float w3  = weights[96 + lane];

    const bool hasExtra = (lane < GITEMS_ - 32);   // lanes 0..7

    // prologue: first group's indices (2 coalesced LDGs)
    int g  = gwarp;
    int i0 = nb[g * GITEMS_ + lane];
    int i1 = hasExtra ? nb[g * GITEMS_ + 32 + lane] : 0;

    #pragma unroll 1
    for (int it = 0; it < GPW_; it++) {
        const int r0    = g * GR_;
        const int vbase = (r0 >> 13) * (V_ * 3);   // groups never span batches

        // 1) prefetch next group's indices (independent LDGs go in flight)
        const int gn = g + NWARPS_;
        int n0 = 0, n1 = 0;
        if (it + 1 < GPW_) {
            const int gbn = gn * GITEMS_;
            n0 = nb[gbn + lane];
            if (hasExtra) n1 = nb[gbn + 32 + lane];
        }

        // 2) batched gather for current group (idx already resident)
        {
            const int   row0 = (lane >= N_);           // item = lane
            const float* p0  = verts + vbase + i0 * 3;
            const float* q0  = verts + (r0 + row0) * 3;
            sd[warp][lane] = make_float4(p0[0]-q0[0], p0[1]-q0[1],
                                         p0[2]-q0[2], 0.0f);
            if (hasExtra) {                            // item = lane+32 -> row 1
                const float* p1 = verts + vbase + i1 * 3;
                const float* q1 = verts + (r0 + 1) * 3;
                sd[warp][lane + 32] = make_float4(p1[0]-q1[0], p1[1]-q1[1],
                                                  p1[2]-q1[2], 0.0f);
            }
        }
        __syncwarp();

        // 3) FUSED compute for both rows: 8 independent max chains,
        //    2 independent LDS.128 per iteration. max seeded 0 == relu.
        float a0=0.f, a1=0.f, a2=0.f, a3=0.f;     // row 0
        float b0=0.f, b1=0.f, b2=0.f, b3=0.f;     // row 1
        {
            const float4* s0 = &sd[warp][0];
            const float4* s1 = &sd[warp][N_];
            #pragma unroll
            for (int j = 0; j < N_; j++) {
                const float4 da = s0[j];
                const float4 db = s1[j];

                float ta0 = fmaf(da.x, d00, fmaf(da.y, d10, da.z * d20));
                float tb0 = fmaf(db.x, d00, fmaf(db.y, d10, db.z * d20));
                float ta1 = fmaf(da.x, d01, fmaf(da.y, d11, da.z * d21));
                float tb1 = fmaf(db.x, d01, fmaf(db.y, d11, db.z * d21));
                float ta2 = fmaf(da.x, d02, fmaf(da.y, d12, da.z * d22));
                float tb2 = fmaf(db.x, d02, fmaf(db.y, d12, db.z * d22));
                float ta3 = fmaf(da.x, d03, fmaf(da.y, d13, da.z * d23));
                float tb3 = fmaf(db.x, d03, fmaf(db.y, d13, db.z * d23));

                a0 = fmaxf(a0, ta0);  b0 = fmaxf(b0, tb0);
                a1 = fmaxf(a1, ta1);  b1 = fmaxf(b1, tb1);
                a2 = fmaxf(a2, ta2);  b2 = fmaxf(b2, tb2);
                a3 = fmaxf(a3, ta3);  b3 = fmaxf(b3, tb3);
            }
        }

        out[ r0      * K_ + lane] = fmaf(a0, w0, fmaf(a1, w1, fmaf(a2, w2, a3 * w3)));
        out[(r0 + 1) * K_ + lane] = fmaf(b0, w0, fmaf(b1, w1, fmaf(b2, w2, b3 * w3)));

        g  = gn;
        i0 = n0;
        i1 = n1;
        __syncwarp();   // protect smem before next group's stores
    }
}

extern "C" void kernel_launch(void* const* d_in, const int* in_sizes, int n_in,
                              void* d_out, int out_size)
{
    const int*   nb      = (const int*)  d_in[0];
    const float* verts   = (const float*)d_in[1];
    const float* weights = (const float*)d_in[2];
    const float* disp    = (const float*)d_in[3];
    float*       out     = (float*)      d_out;

    op3d_kernel<<<BLOCKS_, THREADS_>>>(nb, verts, weights, disp, out);
}